// round 16
// baseline (speedup 1.0000x reference)
#include <cuda_runtime.h>
#include <cuda_fp16.h>
#include <math.h>
#include <cstdint>

#define NCAM 6
#define HW 704
#define NPIX (NCAM*HW)     // 4224
#define KTOT 4608          // 512 * 9
#define DD 112
#define CCTX 80
#define NVOX 16384

// conv3x3 GEMM tiling: 128x128 tile, KC=64, 512 threads
#define KC 64
#define NKC 72
#define ROWB 144
#define MATB (128*ROWB)
#define STGB (2*MATB)
#define NSTG 4
#define SMEM_GEMM (NSTG*STGB)   // 147456

// 1x1 GEMM tiling (KC=32)
#define KC1 32
#define ROWB1 80
#define MATB1 (128*ROWB1)
#define STGB1 (2*MATB1)
#define NSTG1 5
#define SMEM_G1 (NSTG1*STGB1)   // 102400

// ---------------- static scratch ----------------
__device__ __align__(128) __half g_W[4][512*KTOT];
__device__ __align__(128) __half g_X[5][NPIX*512];   // src, x1, x2, hd, hc (fp16 [pix][ci])
__device__ __align__(128) __half g_W1d[DD*512];
__device__ __align__(128) __half g_W1c[CCTX*512];
__device__ __align__(128) float g_vox[NVOX*CCTX];
__device__ float g_logits[NPIX*DD];    // [pix][d]
__device__ float g_ctx[NPIX*CCTX];     // [pix][c]
__device__ float g_Rida[NCAM][9];
__device__ float g_tida[NCAM][3];
__device__ float g_Kinv[NCAM][9];

// ---------------- PTX helpers ----------------
__device__ __forceinline__ uint32_t smem_u32(const void* p) {
    uint32_t a;
    asm("{ .reg .u64 t; cvta.to.shared.u64 t, %1; cvt.u32.u64 %0, t; }" : "=r"(a) : "l"(p));
    return a;
}
__device__ __forceinline__ void cp16(uint32_t dst, const void* src) {
    asm volatile("cp.async.cg.shared.global [%0], [%1], 16;"
                 :: "r"(dst), "l"(__cvta_generic_to_global(src)) : "memory");
}
__device__ __forceinline__ void cp16z(uint32_t dst, const void* src, int sz) {
    asm volatile("cp.async.cg.shared.global [%0], [%1], 16, %2;"
                 :: "r"(dst), "l"(__cvta_generic_to_global(src)), "r"(sz) : "memory");
}
#define CP_COMMIT() asm volatile("cp.async.commit_group;" ::: "memory")
#define CP_WAIT1()  asm volatile("cp.async.wait_group 1;" ::: "memory")
#define CP_WAIT2()  asm volatile("cp.async.wait_group 2;" ::: "memory")
#define CP_WAIT3()  asm volatile("cp.async.wait_group 3;" ::: "memory")

__device__ __forceinline__ void lds_x4(uint32_t a, uint32_t r[4]) {
    asm volatile("ldmatrix.sync.aligned.m8n8.x4.shared.b16 {%0,%1,%2,%3}, [%4];"
                 : "=r"(r[0]), "=r"(r[1]), "=r"(r[2]), "=r"(r[3]) : "r"(a));
}
__device__ __forceinline__ void lds_x2(uint32_t a, uint32_t r[2]) {
    asm volatile("ldmatrix.sync.aligned.m8n8.x2.shared.b16 {%0,%1}, [%2];"
                 : "=r"(r[0]), "=r"(r[1]) : "r"(a));
}
__device__ __forceinline__ void mma16816(float c[4], const uint32_t a[4], const uint32_t b[2]) {
    asm volatile("mma.sync.aligned.m16n8k16.row.col.f32.f16.f16.f32 "
                 "{%0,%1,%2,%3},{%4,%5,%6,%7},{%8,%9},{%0,%1,%2,%3};"
                 : "+f"(c[0]), "+f"(c[1]), "+f"(c[2]), "+f"(c[3])
                 : "r"(a[0]), "r"(a[1]), "r"(a[2]), "r"(a[3]), "r"(b[0]), "r"(b[1]));
}

// ---------------- layout prep ----------------
__global__ void split_src(const float* __restrict__ in) {
    __shared__ float t[32][33];
    const int hw0 = blockIdx.x * 32, ci0 = blockIdx.y * 32, cam = blockIdx.z;
    const int tx = threadIdx.x, ty = threadIdx.y;
#pragma unroll
    for (int i = 0; i < 4; ++i) {
        int ci = ci0 + ty + i * 8;
        t[ty + i * 8][tx] = in[((size_t)(cam * 512 + ci)) * HW + hw0 + tx];
    }
    __syncthreads();
#pragma unroll
    for (int i = 0; i < 4; ++i) {
        int hw = hw0 + ty + i * 8;
        g_X[0][((size_t)cam * HW + hw) * 512 + ci0 + tx] = __float2half_rn(t[tx][ty + i * 8]);
    }
}
__global__ void prep_all_w(const float* __restrict__ w0, const float* __restrict__ w1,
                           const float* __restrict__ w2, const float* __restrict__ w3) {
    int idx = blockIdx.x * blockDim.x + threadIdx.x;
    if (idx >= 4 * 512 * 512) return;
    int layer = idx >> 18;
    int rem = idx & 262143;
    int m = rem >> 9, ci = rem & 511;
    const float* w = (layer == 0) ? w0 : (layer == 1) ? w1 : (layer == 2) ? w2 : w3;
    const float* src = w + ((size_t)m * 512 + ci) * 9;
    __half* dh = &g_W[layer][(size_t)m * KTOT + ci];
#pragma unroll
    for (int pos = 0; pos < 9; ++pos)
        dh[pos * 512] = __float2half_rn(src[pos]);
}
__global__ void prep_w1(const float* __restrict__ wd, const float* __restrict__ wc) {
    int idx = blockIdx.x * blockDim.x + threadIdx.x;
    if (idx < DD * 512) g_W1d[idx] = __float2half_rn(wd[idx]);
    if (idx < CCTX * 512) g_W1c[idx] = __float2half_rn(wc[idx]);
}

// ---------------- conv3x3 implicit GEMM (fp16, KC=64, optional dual weight set) ----------------
__device__ __forceinline__ void produce_stage(uint32_t stg, int kc, int m0, int n0,
                                              const __half* __restrict__ W,
                                              const __half* __restrict__ X,
                                              int tid) {
    const int r = tid & 127;
    if (tid < 128) {
        const char* src = (const char*)(W + (size_t)(m0 + r) * KTOT + kc * KC);
        uint32_t dst = stg + r * ROWB;
#pragma unroll
        for (int i = 0; i < 8; ++i) cp16(dst + i * 16, src + i * 16);
    } else if (tid < 256) {
        const int pos = kc >> 3;
        const int ci0 = (kc & 7) * KC;
        const int n = n0 + r;
        const int cam = n / HW, hw = n % HW;
        const int h = hw / 44, w = hw % 44;
        const int hp = h + pos / 3 - 1, wp = w + pos % 3 - 1;
        const bool valid = (hp >= 0) & (hp < 16) & (wp >= 0) & (wp < 44);
        const int hpc = valid ? hp : 0, wpc = valid ? wp : 0;
        const char* src = (const char*)(X + ((size_t)cam * HW + hpc * 44 + wpc) * 512 + ci0);
        uint32_t dst = stg + MATB + r * ROWB;
        const int sz = valid ? 16 : 0;
#pragma unroll
        for (int i = 0; i < 8; ++i) cp16z(dst + i * 16, src + i * 16, sz);
    }
}

struct Frags { uint32_t A[2][4], B[4][2]; };

__device__ __forceinline__ void load_frags(Frags& f, uint32_t stg, uint32_t kb,
                                           uint32_t a_off, uint32_t b_off) {
#pragma unroll
    for (int im = 0; im < 2; ++im)
        lds_x4(stg + a_off + (uint32_t)(im * 16 * ROWB) + kb, f.A[im]);
#pragma unroll
    for (int nb = 0; nb < 4; ++nb)
        lds_x2(stg + MATB + b_off + (uint32_t)(nb * 8 * ROWB) + kb, f.B[nb]);
}
__device__ __forceinline__ void mma_all(float c[2][4][4], const Frags& f) {
#pragma unroll
    for (int im = 0; im < 2; ++im)
#pragma unroll
        for (int nb = 0; nb < 4; ++nb) mma16816(c[im][nb], f.A[im], f.B[nb]);
}

__global__ void __launch_bounds__(512, 1) gemm_conv(const __half* __restrict__ X,
                                                    const __half* __restrict__ Wa,
                                                    const __half* __restrict__ Wb,
                                                    __half* __restrict__ outA,
                                                    __half* __restrict__ outB,
                                                    int dual) {
    extern __shared__ char smem[];
    const uint32_t sb = smem_u32(smem);
    const int tid = threadIdx.x;
    const int lane = tid & 31, wid = tid >> 5;
    const int which = dual ? (blockIdx.x >> 2) : 0;
    const int m0 = (dual ? (blockIdx.x & 3) : blockIdx.x) * 128;
    const int n0 = blockIdx.y * 128;
    const __half* W = which ? Wb : Wa;
    __half* outX = which ? outB : outA;
    const int warp_m = (wid & 3) * 32;
    const int warp_n = (wid >> 2) * 32;

    float c[2][4][4];
#pragma unroll
    for (int im = 0; im < 2; ++im)
#pragma unroll
        for (int in = 0; in < 4; ++in)
#pragma unroll
            for (int j = 0; j < 4; ++j) c[im][in][j] = 0.f;

    const uint32_t a_off = (uint32_t)((warp_m + (lane & 15)) * ROWB + ((lane >> 4) << 4));
    const uint32_t b_off = (uint32_t)((warp_n + (lane & 7)) * ROWB + (((lane >> 3) & 1) << 4));

#pragma unroll
    for (int s = 0; s < 3; ++s) {
        produce_stage(sb + s * STGB, s, m0, n0, W, X, tid);
        CP_COMMIT();
    }
    CP_WAIT2();
    __syncthreads();

    Frags f, g;
    load_frags(f, sb, 0, a_off, b_off);

#pragma unroll 1
    for (int t = 0; t < NKC; ++t) {
        const uint32_t stg = sb + (t & 3) * STGB;
        load_frags(g, stg, 32, a_off, b_off);  mma_all(c, f);
        load_frags(f, stg, 64, a_off, b_off);  mma_all(c, g);
        load_frags(g, stg, 96, a_off, b_off);  mma_all(c, f);
        if (t + 1 < NKC) {
            CP_WAIT1();
            __syncthreads();
            if (t + 3 < NKC)
                produce_stage(sb + ((t + 3) & 3) * STGB, t + 3, m0, n0, W, X, tid);
            CP_COMMIT();
            load_frags(f, sb + ((t + 1) & 3) * STGB, 0, a_off, b_off);
        }
        mma_all(c, g);
    }

    const int r0 = lane >> 2, c0 = (lane & 3) * 2;
#pragma unroll
    for (int im = 0; im < 2; ++im) {
#pragma unroll
        for (int in = 0; in < 4; ++in) {
            const int m = m0 + warp_m + im * 16 + r0;
            const int n = n0 + warp_n + in * 8 + c0;
            outX[(size_t)n * 512 + m]           = __float2half_rn(fmaxf(c[im][in][0], 0.f));
            outX[(size_t)(n + 1) * 512 + m]     = __float2half_rn(fmaxf(c[im][in][1], 0.f));
            outX[(size_t)n * 512 + m + 8]       = __float2half_rn(fmaxf(c[im][in][2], 0.f));
            outX[(size_t)(n + 1) * 512 + m + 8] = __float2half_rn(fmaxf(c[im][in][3], 0.f));
        }
    }
}

// ---------------- merged 1x1 conv GEMM; outputs [pix][co] ----------------
__device__ __forceinline__ void produce_stage_1x1(uint32_t stg, int kc, int n0, int CO,
                                                  const __half* __restrict__ W1,
                                                  const __half* __restrict__ X, int tid) {
    const int r = tid & 127;
    if (tid < 128) {
        const int rc = (r < CO) ? r : 0;
        const int sz = (r < CO) ? 16 : 0;
        const char* src = (const char*)(W1 + (size_t)rc * 512 + kc * KC1);
        uint32_t dst = stg + r * ROWB1;
#pragma unroll
        for (int i = 0; i < 4; ++i) cp16z(dst + i * 16, src + i * 16, sz);
    } else if (tid < 256) {
        const char* src = (const char*)(X + (size_t)(n0 + r) * 512 + kc * KC1);
        uint32_t dst = stg + MATB1 + r * ROWB1;
#pragma unroll
        for (int i = 0; i < 4; ++i) cp16(dst + i * 16, src + i * 16);
    }
}
__device__ __forceinline__ void load_frags_1x1(Frags& f, uint32_t stg, uint32_t kb,
                                               uint32_t a_off, uint32_t b_off) {
#pragma unroll
    for (int im = 0; im < 2; ++im)
        lds_x4(stg + a_off + (uint32_t)(im * 16 * ROWB1) + kb, f.A[im]);
#pragma unroll
    for (int nb = 0; nb < 4; ++nb)
        lds_x2(stg + MATB1 + b_off + (uint32_t)(nb * 8 * ROWB1) + kb, f.B[nb]);
}

__global__ void __launch_bounds__(512, 1) gemm_1x1(const __half* __restrict__ Xd,
                                                   const __half* __restrict__ Xc,
                                                   const __half* __restrict__ W1d,
                                                   const __half* __restrict__ W1c,
                                                   const float* __restrict__ bd,
                                                   const float* __restrict__ bc,
                                                   float* __restrict__ outd,
                                                   float* __restrict__ outc) {
    extern __shared__ char smem[];
    const uint32_t sb = smem_u32(smem);
    const int tid = threadIdx.x;
    const int lane = tid & 31, wid = tid >> 5;
    const int which = blockIdx.y;
    const __half* X = which ? Xc : Xd;
    const __half* W1 = which ? W1c : W1d;
    const float* bias = which ? bc : bd;
    float* out = which ? outc : outd;
    const int CO = which ? CCTX : DD;
    const int n0 = blockIdx.x * 128;
    const int warp_m = (wid & 3) * 32;
    const int warp_n = (wid >> 2) * 32;
    const int NK1 = 16;

    float c[2][4][4];
#pragma unroll
    for (int im = 0; im < 2; ++im)
#pragma unroll
        for (int in = 0; in < 4; ++in)
#pragma unroll
            for (int j = 0; j < 4; ++j) c[im][in][j] = 0.f;

    const uint32_t a_off = (uint32_t)((warp_m + (lane & 15)) * ROWB1 + ((lane >> 4) << 4));
    const uint32_t b_off = (uint32_t)((warp_n + (lane & 7)) * ROWB1 + (((lane >> 3) & 1) << 4));

#pragma unroll
    for (int s = 0; s < 4; ++s) {
        produce_stage_1x1(sb + s * STGB1, s, n0, CO, W1, X, tid);
        CP_COMMIT();
    }
    CP_WAIT3();
    __syncthreads();

    Frags f, g;
    load_frags_1x1(f, sb, 0, a_off, b_off);

#pragma unroll 1
    for (int t = 0; t < NK1; ++t) {
        const uint32_t stg = sb + (t % NSTG1) * STGB1;
        load_frags_1x1(g, stg, 32, a_off, b_off);
        mma_all(c, f);
        if (t + 1 < NK1) {
            CP_WAIT2();
            __syncthreads();
            if (t + 4 < NK1)
                produce_stage_1x1(sb + ((t + 4) % NSTG1) * STGB1, t + 4, n0, CO, W1, X, tid);
            CP_COMMIT();
            load_frags_1x1(f, sb + ((t + 1) % NSTG1) * STGB1, 0, a_off, b_off);
        }
        mma_all(c, g);
    }

    // epilogue: +bias, store [pix][co]
    const int r0 = lane >> 2, c0 = (lane & 3) * 2;
#pragma unroll
    for (int im = 0; im < 2; ++im) {
#pragma unroll
        for (int in = 0; in < 4; ++in) {
            const int m = warp_m + im * 16 + r0;
            const int n = n0 + warp_n + in * 8 + c0;
            if (m < CO) {
                float b = bias[m];
                out[(size_t)n * CO + m]       = c[im][in][0] + b;
                out[(size_t)(n + 1) * CO + m] = c[im][in][1] + b;
            }
            if (m + 8 < CO) {
                float b = bias[m + 8];
                out[(size_t)n * CO + m + 8]       = c[im][in][2] + b;
                out[(size_t)(n + 1) * CO + m + 8] = c[im][in][3] + b;
            }
        }
    }
}

// ---------------- camera params ----------------
__device__ void inv4x4(const float* M, float* out) {
    float a[4][8];
    for (int i = 0; i < 4; ++i)
        for (int j = 0; j < 4; ++j) { a[i][j] = M[i*4+j]; a[i][4+j] = (i == j) ? 1.f : 0.f; }
    for (int col = 0; col < 4; ++col) {
        int piv = col;
        for (int r = col + 1; r < 4; ++r)
            if (fabsf(a[r][col]) > fabsf(a[piv][col])) piv = r;
        if (piv != col)
            for (int j = 0; j < 8; ++j) { float t = a[col][j]; a[col][j] = a[piv][j]; a[piv][j] = t; }
        float pv = a[col][col];
        for (int j = 0; j < 8; ++j) a[col][j] /= pv;
        for (int r = 0; r < 4; ++r) {
            if (r == col) continue;
            float f = a[r][col];
            for (int j = 0; j < 8; ++j) a[r][j] -= f * a[col][j];
        }
    }
    for (int i = 0; i < 4; ++i)
        for (int j = 0; j < 4; ++j) out[i*4+j] = a[i][4+j];
}
__global__ void cam_params_kernel(const float* __restrict__ ida, const float* __restrict__ intr) {
    int n = threadIdx.x;
    if (n >= NCAM) return;
    float inv[16];
    inv4x4(ida + n * 16, inv);
    for (int i = 0; i < 3; ++i) {
        for (int j = 0; j < 3; ++j) g_Rida[n][i*3+j] = inv[i*4+j];
        g_tida[n][i] = inv[i*4+3];
    }
    const float* K = intr + n * 16;
    float a=K[0],b=K[1],c=K[2],d=K[4],e=K[5],f=K[6],g=K[8],h=K[9],ii=K[10];
    float A=e*ii-f*h, B=-(d*ii-f*g), C=d*h-e*g;
    float det=a*A+b*B+c*C;
    g_Kinv[n][0]=A/det;  g_Kinv[n][1]=(c*h-b*ii)/det; g_Kinv[n][2]=(b*f-c*e)/det;
    g_Kinv[n][3]=B/det;  g_Kinv[n][4]=(a*ii-c*g)/det; g_Kinv[n][5]=(c*d-a*f)/det;
    g_Kinv[n][6]=C/det;  g_Kinv[n][7]=(b*g-a*h)/det;  g_Kinv[n][8]=(a*e-b*d)/det;
}

// ---------------- fused geometry + softmax + scatter ----------------
__global__ void __launch_bounds__(128) scatter_kernel(const float* __restrict__ s2e,
                                                      const float* __restrict__ bda) {
    __shared__ float sred[128];
    __shared__ float sp[DD];
    __shared__ int   svi[DD];
    const int hw = blockIdx.x;
    const int n = blockIdx.y;
    const int tid = threadIdx.x;   // = d

    {
        const int w = hw % 44, h = hw / 44;
        const float ustep = 703.0f / 43.0f;
        const float dstep = 56.0f / 111.0f;
        float u = (w == 43) ? 703.0f : w * ustep;
        float v = (h == 15) ? 255.0f : h * 17.0f;
        float dv = (tid == 111) ? 58.0f : 2.0f + tid * dstep;
        const float* R = g_Rida[n]; const float* t = g_tida[n]; const float* K = g_Kinv[n];
        float p0 = R[0]*u + R[1]*v + R[2] + t[0];
        float p1 = R[3]*u + R[4]*v + R[5] + t[1];
        float p2 = R[6]*u + R[7]*v + R[8] + t[2];
        float r0 = K[0]*p0 + K[1]*p1 + K[2]*p2;
        float r1 = K[3]*p0 + K[4]*p1 + K[5]*p2;
        float r2 = K[6]*p0 + K[7]*p1 + K[8]*p2;
        float c0 = r0*dv, c1 = r1*dv, c2 = r2*dv;
        const float* S = s2e + n * 16;
        float e0 = S[0]*c0 + S[1]*c1 + S[2]*c2 + S[3];
        float e1 = S[4]*c0 + S[5]*c1 + S[6]*c2 + S[7];
        float e2 = S[8]*c0 + S[9]*c1 + S[10]*c2 + S[11];
        float e3 = S[12]*c0 + S[13]*c1 + S[14]*c2 + S[15];
        float b0 = bda[0]*e0 + bda[1]*e1 + bda[2]*e2 + bda[3]*e3;
        float b1 = bda[4]*e0 + bda[5]*e1 + bda[6]*e2 + bda[7]*e3;
        float b2 = bda[8]*e0 + bda[9]*e1 + bda[10]*e2 + bda[11]*e3;
        const float vcx = (float)(-51.2 + 0.4);
        const float vcz = (float)(-5.0 + 4.0);
        const float ox = vcx - 0.8f * 0.5f;
        const float oz = vcz - 8.0f * 0.5f;
        int gx = (int)((b0 - ox) / 0.8f);
        int gy = (int)((b1 - ox) / 0.8f);
        int gz = (int)((b2 - oz) / 8.0f);
        bool valid = (gx >= 0) && (gx < 128) && (gy >= 0) && (gy < 128) && (gz == 0);
        svi[tid] = valid ? (gy * 128 + gx) : -1;
    }

    // ---- softmax over d (coalesced [pix][d] read) ----
    const float l = g_logits[((size_t)n * HW + hw) * DD + tid];
    sred[tid] = l;
    if (tid < 16) sred[112 + tid] = -1e30f;
    __syncthreads();
#pragma unroll
    for (int off = 64; off > 0; off >>= 1) {
        if (tid < off) sred[tid] = fmaxf(sred[tid], sred[tid + off]);
        __syncthreads();
    }
    const float m = sred[0];
    __syncthreads();
    const float e = expf(l - m);
    sred[tid] = e;
    if (tid < 16) sred[112 + tid] = 0.f;
    __syncthreads();
#pragma unroll
    for (int off = 64; off > 0; off >>= 1) {
        if (tid < off) sred[tid] += sred[tid + off];
        __syncthreads();
    }
    sp[tid] = e * (1.0f / sred[0]);
    __syncthreads();

    // ---- scatter (80 channel threads; coalesced ctx read) ----
    if (tid < CCTX) {
        const float ctx = g_ctx[((size_t)n * HW + hw) * CCTX + tid];
        int cur = -1; float pacc = 0.f;
#pragma unroll 8
        for (int d = 0; d < DD; ++d) {
            int idx = svi[d];
            float p = sp[d];
            if (idx == cur) pacc += p;
            else {
                if (cur >= 0) atomicAdd(&g_vox[cur * CCTX + tid], pacc * ctx);
                cur = idx; pacc = p;
            }
        }
        if (cur >= 0) atomicAdd(&g_vox[cur * CCTX + tid], pacc * ctx);
    }
}

// ---------------- tiled transpose [vox][c] -> out[c][vox] ----------------
__global__ void __launch_bounds__(256) vox_to_out(float* __restrict__ out) {
    __shared__ float t[64 * CCTX];
    const int v0 = blockIdx.x * 64;
    const int tid = threadIdx.x;
    for (int j = tid; j < 64 * CCTX; j += 256) t[j] = g_vox[(size_t)v0 * CCTX + j];
    __syncthreads();
    for (int j = tid; j < 64 * CCTX; j += 256) {
        int c = j >> 6, dv = j & 63;
        out[(size_t)c * NVOX + v0 + dv] = t[dv * CCTX + c];
    }
}

// ---------------- launch ----------------
extern "C" void kernel_launch(void* const* d_in, const int* in_sizes, int n_in,
                              void* d_out, int out_size) {
    const float* src  = (const float*)d_in[0];
    const float* w_s1 = (const float*)d_in[1];
    const float* w_s2 = (const float*)d_in[2];
    const float* w_d1 = (const float*)d_in[3];
    const float* w_d2 = (const float*)d_in[4];
    const float* b_d  = (const float*)d_in[5];
    const float* w_c1 = (const float*)d_in[6];
    const float* w_c2 = (const float*)d_in[7];
    const float* b_c  = (const float*)d_in[8];
    const float* s2e  = (const float*)d_in[9];
    const float* intr = (const float*)d_in[10];
    const float* ida  = (const float*)d_in[11];
    const float* bda  = (const float*)d_in[12];

    __half *W, *X, *W1d, *W1c;
    float *logits, *ctx, *vox;
    cudaGetSymbolAddress((void**)&W, g_W);
    cudaGetSymbolAddress((void**)&X, g_X);
    cudaGetSymbolAddress((void**)&W1d, g_W1d);
    cudaGetSymbolAddress((void**)&W1c, g_W1c);
    cudaGetSymbolAddress((void**)&logits, g_logits);
    cudaGetSymbolAddress((void**)&ctx, g_ctx);
    cudaGetSymbolAddress((void**)&vox, g_vox);

    const size_t WSZ = (size_t)512 * KTOT;
    const size_t XSZ = (size_t)NPIX * 512;

    cudaFuncSetAttribute(gemm_conv, cudaFuncAttributeMaxDynamicSharedMemorySize, SMEM_GEMM);
    cudaFuncSetAttribute(gemm_1x1, cudaFuncAttributeMaxDynamicSharedMemorySize, SMEM_G1);

    split_src<<<dim3(HW / 32, 512 / 32, NCAM), dim3(32, 8)>>>(src);
    prep_all_w<<<(4 * 512 * 512 + 255) / 256, 256>>>(w_s1, w_s2, w_d1, w_c1);
    prep_w1<<<(DD * 512 + 255) / 256, 256>>>(w_d2, w_c2);
    cam_params_kernel<<<1, 32>>>(ida, intr);
    cudaMemsetAsync(vox, 0, (size_t)NVOX * CCTX * sizeof(float), 0);

    gemm_conv<<<dim3(4, 33), 512, SMEM_GEMM>>>(X, W, W, X + XSZ, X + XSZ, 0);
    gemm_conv<<<dim3(4, 33), 512, SMEM_GEMM>>>(X + XSZ, W + WSZ, W + WSZ,
                                               X + 2 * XSZ, X + 2 * XSZ, 0);
    gemm_conv<<<dim3(8, 33), 512, SMEM_GEMM>>>(X + 2 * XSZ, W + 2 * WSZ, W + 3 * WSZ,
                                               X + 3 * XSZ, X + 4 * XSZ, 1);

    gemm_1x1<<<dim3(33, 2), 512, SMEM_G1>>>(X + 3 * XSZ, X + 4 * XSZ,
                                            W1d, W1c, b_d, b_c, logits, ctx);

    scatter_kernel<<<dim3(HW, NCAM), 112>>>(s2e, bda);
    vox_to_out<<<NVOX / 64, 256>>>((float*)d_out);
}

// round 17
// speedup vs baseline: 1.4900x; 1.4900x over previous
#include <cuda_runtime.h>
#include <cuda_fp16.h>
#include <math.h>
#include <cstdint>

#define NCAM 6
#define HW 704
#define NPIX (NCAM*HW)     // 4224
#define KTOT 4608          // 512 * 9
#define DD 112
#define CCTX 80
#define NVOX 16384

// conv3x3 GEMM tiling: 128x128 tile, KC=64, 512 threads
#define KC 64
#define NKC 72
#define ROWB 144
#define MATB (128*ROWB)
#define STGB (2*MATB)
#define NSTG 4
#define SMEM_GEMM (NSTG*STGB)   // 147456

// 1x1 GEMM tiling (KC=32)
#define KC1 32
#define ROWB1 80
#define MATB1 (128*ROWB1)
#define STGB1 (2*MATB1)
#define NSTG1 5
#define SMEM_G1 (NSTG1*STGB1)   // 102400

// ---------------- static scratch ----------------
__device__ __align__(128) __half g_W[4][512*KTOT];
__device__ __align__(128) __half g_X[5][NPIX*512];   // src, x1, x2, hd, hc (fp16 [pix][ci])
__device__ __align__(128) __half g_W1d[DD*512];
__device__ __align__(128) __half g_W1c[CCTX*512];
__device__ __align__(128) float g_vox[NVOX*CCTX];
__device__ float g_logits[NPIX*DD];    // [pix][d]
__device__ float g_ctx[NPIX*CCTX];     // [pix][c]
__device__ float g_Rida[NCAM][9];
__device__ float g_tida[NCAM][3];
__device__ float g_Kinv[NCAM][9];

// ---------------- PTX helpers ----------------
__device__ __forceinline__ uint32_t smem_u32(const void* p) {
    uint32_t a;
    asm("{ .reg .u64 t; cvta.to.shared.u64 t, %1; cvt.u32.u64 %0, t; }" : "=r"(a) : "l"(p));
    return a;
}
__device__ __forceinline__ void cp16(uint32_t dst, const void* src) {
    asm volatile("cp.async.cg.shared.global [%0], [%1], 16;"
                 :: "r"(dst), "l"(__cvta_generic_to_global(src)) : "memory");
}
__device__ __forceinline__ void cp16z(uint32_t dst, const void* src, int sz) {
    asm volatile("cp.async.cg.shared.global [%0], [%1], 16, %2;"
                 :: "r"(dst), "l"(__cvta_generic_to_global(src)), "r"(sz) : "memory");
}
#define CP_COMMIT() asm volatile("cp.async.commit_group;" ::: "memory")
#define CP_WAIT1()  asm volatile("cp.async.wait_group 1;" ::: "memory")
#define CP_WAIT2()  asm volatile("cp.async.wait_group 2;" ::: "memory")
#define CP_WAIT3()  asm volatile("cp.async.wait_group 3;" ::: "memory")

__device__ __forceinline__ void lds_x4(uint32_t a, uint32_t r[4]) {
    asm volatile("ldmatrix.sync.aligned.m8n8.x4.shared.b16 {%0,%1,%2,%3}, [%4];"
                 : "=r"(r[0]), "=r"(r[1]), "=r"(r[2]), "=r"(r[3]) : "r"(a));
}
__device__ __forceinline__ void lds_x2(uint32_t a, uint32_t r[2]) {
    asm volatile("ldmatrix.sync.aligned.m8n8.x2.shared.b16 {%0,%1}, [%2];"
                 : "=r"(r[0]), "=r"(r[1]) : "r"(a));
}
__device__ __forceinline__ void mma16816(float c[4], const uint32_t a[4], const uint32_t b[2]) {
    asm volatile("mma.sync.aligned.m16n8k16.row.col.f32.f16.f16.f32 "
                 "{%0,%1,%2,%3},{%4,%5,%6,%7},{%8,%9},{%0,%1,%2,%3};"
                 : "+f"(c[0]), "+f"(c[1]), "+f"(c[2]), "+f"(c[3])
                 : "r"(a[0]), "r"(a[1]), "r"(a[2]), "r"(a[3]), "r"(b[0]), "r"(b[1]));
}

// ---------------- layout prep ----------------
__global__ void split_src(const float* __restrict__ in) {
    __shared__ float t[32][33];
    const int hw0 = blockIdx.x * 32, ci0 = blockIdx.y * 32, cam = blockIdx.z;
    const int tx = threadIdx.x, ty = threadIdx.y;
#pragma unroll
    for (int i = 0; i < 4; ++i) {
        int ci = ci0 + ty + i * 8;
        t[ty + i * 8][tx] = in[((size_t)(cam * 512 + ci)) * HW + hw0 + tx];
    }
    __syncthreads();
#pragma unroll
    for (int i = 0; i < 4; ++i) {
        int hw = hw0 + ty + i * 8;
        g_X[0][((size_t)cam * HW + hw) * 512 + ci0 + tx] = __float2half_rn(t[tx][ty + i * 8]);
    }
}
__global__ void prep_all_w(const float* __restrict__ w0, const float* __restrict__ w1,
                           const float* __restrict__ w2, const float* __restrict__ w3) {
    int idx = blockIdx.x * blockDim.x + threadIdx.x;
    if (idx >= 4 * 512 * 512) return;
    int layer = idx >> 18;
    int rem = idx & 262143;
    int m = rem >> 9, ci = rem & 511;
    const float* w = (layer == 0) ? w0 : (layer == 1) ? w1 : (layer == 2) ? w2 : w3;
    const float* src = w + ((size_t)m * 512 + ci) * 9;
    __half* dh = &g_W[layer][(size_t)m * KTOT + ci];
#pragma unroll
    for (int pos = 0; pos < 9; ++pos)
        dh[pos * 512] = __float2half_rn(src[pos]);
}
__global__ void prep_w1(const float* __restrict__ wd, const float* __restrict__ wc) {
    int idx = blockIdx.x * blockDim.x + threadIdx.x;
    if (idx < DD * 512) g_W1d[idx] = __float2half_rn(wd[idx]);
    if (idx < CCTX * 512) g_W1c[idx] = __float2half_rn(wc[idx]);
}

// ---------------- conv3x3 implicit GEMM (fp16, KC=64) ----------------
__device__ __forceinline__ void produce_stage(uint32_t stg, int kc, int m0, int n0,
                                              const __half* __restrict__ W,
                                              const __half* __restrict__ X,
                                              int tid) {
    const int r = tid & 127;
    if (tid < 128) {
        const char* src = (const char*)(W + (size_t)(m0 + r) * KTOT + kc * KC);
        uint32_t dst = stg + r * ROWB;
#pragma unroll
        for (int i = 0; i < 8; ++i) cp16(dst + i * 16, src + i * 16);
    } else if (tid < 256) {
        const int pos = kc >> 3;
        const int ci0 = (kc & 7) * KC;
        const int n = n0 + r;
        const int cam = n / HW, hw = n % HW;
        const int h = hw / 44, w = hw % 44;
        const int hp = h + pos / 3 - 1, wp = w + pos % 3 - 1;
        const bool valid = (hp >= 0) & (hp < 16) & (wp >= 0) & (wp < 44);
        const int hpc = valid ? hp : 0, wpc = valid ? wp : 0;
        const char* src = (const char*)(X + ((size_t)cam * HW + hpc * 44 + wpc) * 512 + ci0);
        uint32_t dst = stg + MATB + r * ROWB;
        const int sz = valid ? 16 : 0;
#pragma unroll
        for (int i = 0; i < 8; ++i) cp16z(dst + i * 16, src + i * 16, sz);
    }
}

struct Frags { uint32_t A[2][4], B[4][2]; };

__device__ __forceinline__ void load_frags(Frags& f, uint32_t stg, uint32_t kb,
                                           uint32_t a_off, uint32_t b_off) {
#pragma unroll
    for (int im = 0; im < 2; ++im)
        lds_x4(stg + a_off + (uint32_t)(im * 16 * ROWB) + kb, f.A[im]);
#pragma unroll
    for (int nb = 0; nb < 4; ++nb)
        lds_x2(stg + MATB + b_off + (uint32_t)(nb * 8 * ROWB) + kb, f.B[nb]);
}
__device__ __forceinline__ void mma_all(float c[2][4][4], const Frags& f) {
#pragma unroll
    for (int im = 0; im < 2; ++im)
#pragma unroll
        for (int nb = 0; nb < 4; ++nb) mma16816(c[im][nb], f.A[im], f.B[nb]);
}

__global__ void __launch_bounds__(512, 1) gemm_conv(const __half* __restrict__ X,
                                                    const __half* __restrict__ W,
                                                    __half* __restrict__ outX) {
    extern __shared__ char smem[];
    const uint32_t sb = smem_u32(smem);
    const int tid = threadIdx.x;
    const int lane = tid & 31, wid = tid >> 5;
    const int m0 = blockIdx.x * 128;
    const int n0 = blockIdx.y * 128;
    const int warp_m = (wid & 3) * 32;
    const int warp_n = (wid >> 2) * 32;

    float c[2][4][4];
#pragma unroll
    for (int im = 0; im < 2; ++im)
#pragma unroll
        for (int in = 0; in < 4; ++in)
#pragma unroll
            for (int j = 0; j < 4; ++j) c[im][in][j] = 0.f;

    const uint32_t a_off = (uint32_t)((warp_m + (lane & 15)) * ROWB + ((lane >> 4) << 4));
    const uint32_t b_off = (uint32_t)((warp_n + (lane & 7)) * ROWB + (((lane >> 3) & 1) << 4));

#pragma unroll
    for (int s = 0; s < 3; ++s) {
        produce_stage(sb + s * STGB, s, m0, n0, W, X, tid);
        CP_COMMIT();
    }
    CP_WAIT2();
    __syncthreads();

    Frags f, g;
    load_frags(f, sb, 0, a_off, b_off);

#pragma unroll 1
    for (int t = 0; t < NKC; ++t) {
        const uint32_t stg = sb + (t & 3) * STGB;
        load_frags(g, stg, 32, a_off, b_off);  mma_all(c, f);
        load_frags(f, stg, 64, a_off, b_off);  mma_all(c, g);
        load_frags(g, stg, 96, a_off, b_off);  mma_all(c, f);
        if (t + 1 < NKC) {
            CP_WAIT1();
            __syncthreads();
            if (t + 3 < NKC)
                produce_stage(sb + ((t + 3) & 3) * STGB, t + 3, m0, n0, W, X, tid);
            CP_COMMIT();
            load_frags(f, sb + ((t + 1) & 3) * STGB, 0, a_off, b_off);
        }
        mma_all(c, g);
    }

    const int r0 = lane >> 2, c0 = (lane & 3) * 2;
#pragma unroll
    for (int im = 0; im < 2; ++im) {
#pragma unroll
        for (int in = 0; in < 4; ++in) {
            const int m = m0 + warp_m + im * 16 + r0;
            const int n = n0 + warp_n + in * 8 + c0;
            outX[(size_t)n * 512 + m]           = __float2half_rn(fmaxf(c[im][in][0], 0.f));
            outX[(size_t)(n + 1) * 512 + m]     = __float2half_rn(fmaxf(c[im][in][1], 0.f));
            outX[(size_t)n * 512 + m + 8]       = __float2half_rn(fmaxf(c[im][in][2], 0.f));
            outX[(size_t)(n + 1) * 512 + m + 8] = __float2half_rn(fmaxf(c[im][in][3], 0.f));
        }
    }
}

// ---------------- 1x1 conv GEMM (KC=32); outputs [pix][co] ----------------
__device__ __forceinline__ void produce_stage_1x1(uint32_t stg, int kc, int n0, int CO,
                                                  const __half* __restrict__ W1,
                                                  const __half* __restrict__ X, int tid) {
    const int r = tid & 127;
    if (tid < 128) {
        const int rc = (r < CO) ? r : 0;
        const int sz = (r < CO) ? 16 : 0;
        const char* src = (const char*)(W1 + (size_t)rc * 512 + kc * KC1);
        uint32_t dst = stg + r * ROWB1;
#pragma unroll
        for (int i = 0; i < 4; ++i) cp16z(dst + i * 16, src + i * 16, sz);
    } else if (tid < 256) {
        const char* src = (const char*)(X + (size_t)(n0 + r) * 512 + kc * KC1);
        uint32_t dst = stg + MATB1 + r * ROWB1;
#pragma unroll
        for (int i = 0; i < 4; ++i) cp16(dst + i * 16, src + i * 16);
    }
}
__device__ __forceinline__ void load_frags_1x1(Frags& f, uint32_t stg, uint32_t kb,
                                               uint32_t a_off, uint32_t b_off) {
#pragma unroll
    for (int im = 0; im < 2; ++im)
        lds_x4(stg + a_off + (uint32_t)(im * 16 * ROWB1) + kb, f.A[im]);
#pragma unroll
    for (int nb = 0; nb < 4; ++nb)
        lds_x2(stg + MATB1 + b_off + (uint32_t)(nb * 8 * ROWB1) + kb, f.B[nb]);
}

__global__ void __launch_bounds__(512, 1) gemm_1x1(const __half* __restrict__ X,
                                                   const __half* __restrict__ W1,
                                                   const float* __restrict__ bias,
                                                   float* __restrict__ out, int CO) {
    extern __shared__ char smem[];
    const uint32_t sb = smem_u32(smem);
    const int tid = threadIdx.x;
    const int lane = tid & 31, wid = tid >> 5;
    const int n0 = blockIdx.x * 128;
    const int warp_m = (wid & 3) * 32;
    const int warp_n = (wid >> 2) * 32;
    const int NK1 = 16;

    float c[2][4][4];
#pragma unroll
    for (int im = 0; im < 2; ++im)
#pragma unroll
        for (int in = 0; in < 4; ++in)
#pragma unroll
            for (int j = 0; j < 4; ++j) c[im][in][j] = 0.f;

    const uint32_t a_off = (uint32_t)((warp_m + (lane & 15)) * ROWB1 + ((lane >> 4) << 4));
    const uint32_t b_off = (uint32_t)((warp_n + (lane & 7)) * ROWB1 + (((lane >> 3) & 1) << 4));

#pragma unroll
    for (int s = 0; s < 4; ++s) {
        produce_stage_1x1(sb + s * STGB1, s, n0, CO, W1, X, tid);
        CP_COMMIT();
    }
    CP_WAIT3();
    __syncthreads();

    Frags f, g;
    load_frags_1x1(f, sb, 0, a_off, b_off);

#pragma unroll 1
    for (int t = 0; t < NK1; ++t) {
        const uint32_t stg = sb + (t % NSTG1) * STGB1;
        load_frags_1x1(g, stg, 32, a_off, b_off);
        mma_all(c, f);
        if (t + 1 < NK1) {
            CP_WAIT2();
            __syncthreads();
            if (t + 4 < NK1)
                produce_stage_1x1(sb + ((t + 4) % NSTG1) * STGB1, t + 4, n0, CO, W1, X, tid);
            CP_COMMIT();
            load_frags_1x1(f, sb + ((t + 1) % NSTG1) * STGB1, 0, a_off, b_off);
        }
        mma_all(c, g);
    }

    // epilogue: +bias, store [pix][co] (coalesced scatter feed)
    const int r0 = lane >> 2, c0 = (lane & 3) * 2;
#pragma unroll
    for (int im = 0; im < 2; ++im) {
#pragma unroll
        for (int in = 0; in < 4; ++in) {
            const int m = warp_m + im * 16 + r0;
            const int n = n0 + warp_n + in * 8 + c0;
            if (m < CO) {
                float b = bias[m];
                out[(size_t)n * CO + m]       = c[im][in][0] + b;
                out[(size_t)(n + 1) * CO + m] = c[im][in][1] + b;
            }
            if (m + 8 < CO) {
                float b = bias[m + 8];
                out[(size_t)n * CO + m + 8]       = c[im][in][2] + b;
                out[(size_t)(n + 1) * CO + m + 8] = c[im][in][3] + b;
            }
        }
    }
}

// ---------------- camera params ----------------
__device__ void inv4x4(const float* M, float* out) {
    float a[4][8];
    for (int i = 0; i < 4; ++i)
        for (int j = 0; j < 4; ++j) { a[i][j] = M[i*4+j]; a[i][4+j] = (i == j) ? 1.f : 0.f; }
    for (int col = 0; col < 4; ++col) {
        int piv = col;
        for (int r = col + 1; r < 4; ++r)
            if (fabsf(a[r][col]) > fabsf(a[piv][col])) piv = r;
        if (piv != col)
            for (int j = 0; j < 8; ++j) { float t = a[col][j]; a[col][j] = a[piv][j]; a[piv][j] = t; }
        float pv = a[col][col];
        for (int j = 0; j < 8; ++j) a[col][j] /= pv;
        for (int r = 0; r < 4; ++r) {
            if (r == col) continue;
            float f = a[r][col];
            for (int j = 0; j < 8; ++j) a[r][j] -= f * a[col][j];
        }
    }
    for (int i = 0; i < 4; ++i)
        for (int j = 0; j < 4; ++j) out[i*4+j] = a[i][4+j];
}
__global__ void cam_params_kernel(const float* __restrict__ ida, const float* __restrict__ intr) {
    int n = threadIdx.x;
    if (n >= NCAM) return;
    float inv[16];
    inv4x4(ida + n * 16, inv);
    for (int i = 0; i < 3; ++i) {
        for (int j = 0; j < 3; ++j) g_Rida[n][i*3+j] = inv[i*4+j];
        g_tida[n][i] = inv[i*4+3];
    }
    const float* K = intr + n * 16;
    float a=K[0],b=K[1],c=K[2],d=K[4],e=K[5],f=K[6],g=K[8],h=K[9],ii=K[10];
    float A=e*ii-f*h, B=-(d*ii-f*g), C=d*h-e*g;
    float det=a*A+b*B+c*C;
    g_Kinv[n][0]=A/det;  g_Kinv[n][1]=(c*h-b*ii)/det; g_Kinv[n][2]=(b*f-c*e)/det;
    g_Kinv[n][3]=B/det;  g_Kinv[n][4]=(a*ii-c*g)/det; g_Kinv[n][5]=(c*d-a*f)/det;
    g_Kinv[n][6]=C/det;  g_Kinv[n][7]=(b*g-a*h)/det;  g_Kinv[n][8]=(a*e-b*d)/det;
}

// ---------------- fused geometry + softmax + scatter ----------------
__global__ void __launch_bounds__(128) scatter_kernel(const float* __restrict__ s2e,
                                                      const float* __restrict__ bda) {
    __shared__ float sred[128];
    __shared__ float sp[DD];
    __shared__ int   svi[DD];
    const int hw = blockIdx.x;
    const int n = blockIdx.y;
    const int tid = threadIdx.x;   // = d

    {
        const int w = hw % 44, h = hw / 44;
        const float ustep = 703.0f / 43.0f;
        const float dstep = 56.0f / 111.0f;
        float u = (w == 43) ? 703.0f : w * ustep;
        float v = (h == 15) ? 255.0f : h * 17.0f;
        float dv = (tid == 111) ? 58.0f : 2.0f + tid * dstep;
        const float* R = g_Rida[n]; const float* t = g_tida[n]; const float* K = g_Kinv[n];
        float p0 = R[0]*u + R[1]*v + R[2] + t[0];
        float p1 = R[3]*u + R[4]*v + R[5] + t[1];
        float p2 = R[6]*u + R[7]*v + R[8] + t[2];
        float r0 = K[0]*p0 + K[1]*p1 + K[2]*p2;
        float r1 = K[3]*p0 + K[4]*p1 + K[5]*p2;
        float r2 = K[6]*p0 + K[7]*p1 + K[8]*p2;
        float c0 = r0*dv, c1 = r1*dv, c2 = r2*dv;
        const float* S = s2e + n * 16;
        float e0 = S[0]*c0 + S[1]*c1 + S[2]*c2 + S[3];
        float e1 = S[4]*c0 + S[5]*c1 + S[6]*c2 + S[7];
        float e2 = S[8]*c0 + S[9]*c1 + S[10]*c2 + S[11];
        float e3 = S[12]*c0 + S[13]*c1 + S[14]*c2 + S[15];
        float b0 = bda[0]*e0 + bda[1]*e1 + bda[2]*e2 + bda[3]*e3;
        float b1 = bda[4]*e0 + bda[5]*e1 + bda[6]*e2 + bda[7]*e3;
        float b2 = bda[8]*e0 + bda[9]*e1 + bda[10]*e2 + bda[11]*e3;
        const float vcx = (float)(-51.2 + 0.4);
        const float vcz = (float)(-5.0 + 4.0);
        const float ox = vcx - 0.8f * 0.5f;
        const float oz = vcz - 8.0f * 0.5f;
        int gx = (int)((b0 - ox) / 0.8f);
        int gy = (int)((b1 - ox) / 0.8f);
        int gz = (int)((b2 - oz) / 8.0f);
        bool valid = (gx >= 0) && (gx < 128) && (gy >= 0) && (gy < 128) && (gz == 0);
        svi[tid] = valid ? (gy * 128 + gx) : -1;
    }

    // ---- softmax over d (coalesced [pix][d] read) ----
    const float l = g_logits[((size_t)n * HW + hw) * DD + tid];
    sred[tid] = l;
    if (tid < 16) sred[112 + tid] = -1e30f;
    __syncthreads();
#pragma unroll
    for (int off = 64; off > 0; off >>= 1) {
        if (tid < off) sred[tid] = fmaxf(sred[tid], sred[tid + off]);
        __syncthreads();
    }
    const float m = sred[0];
    __syncthreads();
    const float e = expf(l - m);
    sred[tid] = e;
    if (tid < 16) sred[112 + tid] = 0.f;
    __syncthreads();
#pragma unroll
    for (int off = 64; off > 0; off >>= 1) {
        if (tid < off) sred[tid] += sred[tid + off];
        __syncthreads();
    }
    sp[tid] = e * (1.0f / sred[0]);
    __syncthreads();

    // ---- scatter (80 channel threads; coalesced ctx read) ----
    if (tid < CCTX) {
        const float ctx = g_ctx[((size_t)n * HW + hw) * CCTX + tid];
        int cur = -1; float pacc = 0.f;
#pragma unroll 8
        for (int d = 0; d < DD; ++d) {
            int idx = svi[d];
            float p = sp[d];
            if (idx == cur) pacc += p;
            else {
                if (cur >= 0) atomicAdd(&g_vox[cur * CCTX + tid], pacc * ctx);
                cur = idx; pacc = p;
            }
        }
        if (cur >= 0) atomicAdd(&g_vox[cur * CCTX + tid], pacc * ctx);
    }
}

// ---------------- tiled transpose [vox][c] -> out[c][vox] ----------------
__global__ void __launch_bounds__(256) vox_to_out(float* __restrict__ out) {
    __shared__ float t[64 * CCTX];
    const int v0 = blockIdx.x * 64;
    const int tid = threadIdx.x;
    for (int j = tid; j < 64 * CCTX; j += 256) t[j] = g_vox[(size_t)v0 * CCTX + j];
    __syncthreads();
    for (int j = tid; j < 64 * CCTX; j += 256) {
        int c = j >> 6, dv = j & 63;
        out[(size_t)c * NVOX + v0 + dv] = t[dv * CCTX + c];
    }
}

// ---------------- launch ----------------
extern "C" void kernel_launch(void* const* d_in, const int* in_sizes, int n_in,
                              void* d_out, int out_size) {
    const float* src  = (const float*)d_in[0];
    const float* w_s1 = (const float*)d_in[1];
    const float* w_s2 = (const float*)d_in[2];
    const float* w_d1 = (const float*)d_in[3];
    const float* w_d2 = (const float*)d_in[4];
    const float* b_d  = (const float*)d_in[5];
    const float* w_c1 = (const float*)d_in[6];
    const float* w_c2 = (const float*)d_in[7];
    const float* b_c  = (const float*)d_in[8];
    const float* s2e  = (const float*)d_in[9];
    const float* intr = (const float*)d_in[10];
    const float* ida  = (const float*)d_in[11];
    const float* bda  = (const float*)d_in[12];

    __half *W, *X, *W1d, *W1c;
    float *logits, *ctx, *vox;
    cudaGetSymbolAddress((void**)&W, g_W);
    cudaGetSymbolAddress((void**)&X, g_X);
    cudaGetSymbolAddress((void**)&W1d, g_W1d);
    cudaGetSymbolAddress((void**)&W1c, g_W1c);
    cudaGetSymbolAddress((void**)&logits, g_logits);
    cudaGetSymbolAddress((void**)&ctx, g_ctx);
    cudaGetSymbolAddress((void**)&vox, g_vox);

    const size_t WSZ = (size_t)512 * KTOT;
    const size_t XSZ = (size_t)NPIX * 512;

    cudaFuncSetAttribute(gemm_conv, cudaFuncAttributeMaxDynamicSharedMemorySize, SMEM_GEMM);
    cudaFuncSetAttribute(gemm_1x1, cudaFuncAttributeMaxDynamicSharedMemorySize, SMEM_G1);

    split_src<<<dim3(HW / 32, 512 / 32, NCAM), dim3(32, 8)>>>(src);
    prep_all_w<<<(4 * 512 * 512 + 255) / 256, 256>>>(w_s1, w_s2, w_d1, w_c1);
    prep_w1<<<(DD * 512 + 255) / 256, 256>>>(w_d2, w_c2);
    cam_params_kernel<<<1, 32>>>(ida, intr);
    cudaMemsetAsync(vox, 0, (size_t)NVOX * CCTX * sizeof(float), 0);

    dim3 ggrid(4, 33);
    gemm_conv<<<ggrid, 512, SMEM_GEMM>>>(X, W, X + XSZ);
    gemm_conv<<<ggrid, 512, SMEM_GEMM>>>(X + XSZ, W + WSZ, X + 2 * XSZ);
    gemm_conv<<<ggrid, 512, SMEM_GEMM>>>(X + 2 * XSZ, W + 2 * WSZ, X + 3 * XSZ);
    gemm_conv<<<ggrid, 512, SMEM_GEMM>>>(X + 2 * XSZ, W + 3 * WSZ, X + 4 * XSZ);

    gemm_1x1<<<33, 512, SMEM_G1>>>(X + 3 * XSZ, W1d, b_d, logits, DD);
    gemm_1x1<<<33, 512, SMEM_G1>>>(X + 4 * XSZ, W1c, b_c, ctx, CCTX);

    scatter_kernel<<<dim3(HW, NCAM), 112>>>(s2e, bda);
    vox_to_out<<<NVOX / 64, 256>>>((float*)d_out);
}